// round 5
// baseline (speedup 1.0000x reference)
#include <cuda_runtime.h>
#include <cuda_bf16.h>

typedef unsigned long long ull;

#define BB    64
#define TT    512
#define MMM   (BB * TT)

__device__ float g_x0[MMM * 128];
__device__ float g_xg[2u * MMM * 512];
__device__ float g_xgB[BB * 512];
__device__ float g_ya[MMM * 256];
__device__ float g_yb[MMM * 256];
__device__ float g_ylast[BB * 256];

// ---------------------------------------------------------------------------
__device__ __forceinline__ ull pk2(float lo, float hi) {
    ull r; asm("mov.b64 %0, {%1, %2};" : "=l"(r) : "f"(lo), "f"(hi)); return r;
}
__device__ __forceinline__ ull fma2(ull a, ull b, ull c) {
    ull d; asm("fma.rn.f32x2 %0, %1, %2, %3;" : "=l"(d) : "l"(a), "l"(b), "l"(c)); return d;
}
__device__ __forceinline__ float2 upk2(ull v) {
    float2 f; asm("mov.b64 {%0, %1}, %2;" : "=f"(f.x), "=f"(f.y) : "l"(v)); return f;
}
__device__ __forceinline__ float hsum2(ull v) { float2 f = upk2(v); return f.x + f.y; }

__device__ __forceinline__ float tanh_a(float x) {
    float r; asm("tanh.approx.f32 %0, %1;" : "=f"(r) : "f"(x)); return r;
}
__device__ __forceinline__ float sig_a(float x) {
    return fmaf(0.5f, tanh_a(0.5f * x), 0.5f);
}

// ---------------------------------------------------------------------------
// Kernel 1: embedding gather
// ---------------------------------------------------------------------------
__global__ void embed_k(const int* __restrict__ X,
                        const float* __restrict__ emb,
                        float* __restrict__ out) {
    int i = blockIdx.x * blockDim.x + threadIdx.x;
    int m  = i >> 5;
    int e4 = (i & 31) << 2;
    int v  = X[m];
    *reinterpret_cast<float4*>(&out[(size_t)m * 128 + e4]) =
        *reinterpret_cast<const float4*>(&emb[(size_t)v * 128 + e4]);
}

// ---------------------------------------------------------------------------
// Kernel 2: input GEMM. B-broadcast lane mapping: ty = tid&15 (m), tx = tid>>4 (n).
// ---------------------------------------------------------------------------
#define GBM 128
#define GBN 128
#define GBK 16

__global__ __launch_bounds__(256, 2)
void gemm_xw(const float* __restrict__ X,
             const float* __restrict__ Wfull,
             const float* __restrict__ bi,
             const float* __restrict__ bh,
             float* __restrict__ C,
             int K) {
    const int d  = blockIdx.z;
    const float* Wd = Wfull + (size_t)d * 512 * K;
    float* Cd       = C     + (size_t)d * MMM * 512;

    __shared__ float As[2][GBK][GBM];
    __shared__ float Bs[2][GBK][GBN];

    const int m0 = blockIdx.y * GBM;
    const int n0 = blockIdx.x * GBN;
    const int tid = threadIdx.x;
    const int ty = tid & 15;        // m  (varies within half-warp -> A distinct)
    const int tx = tid >> 4;        // n  (constant within half-warp -> B broadcast)

    const int r0l = tid >> 2,          kq0 = (tid & 3) << 2;
    const int r1l = (tid + 256) >> 2,  kq1 = ((tid + 256) & 3) << 2;

    ull acc[8][4];
#pragma unroll
    for (int i = 0; i < 8; i++)
#pragma unroll
        for (int jp = 0; jp < 4; jp++) acc[i][jp] = 0ull;

    float4 av0 = *reinterpret_cast<const float4*>(&X [(size_t)(m0 + r0l) * K + kq0]);
    float4 av1 = *reinterpret_cast<const float4*>(&X [(size_t)(m0 + r1l) * K + kq1]);
    float4 bv0 = *reinterpret_cast<const float4*>(&Wd[(size_t)(n0 + r0l) * K + kq0]);
    float4 bv1 = *reinterpret_cast<const float4*>(&Wd[(size_t)(n0 + r1l) * K + kq1]);
    {
        As[0][kq0 + 0][r0l] = av0.x; As[0][kq0 + 1][r0l] = av0.y;
        As[0][kq0 + 2][r0l] = av0.z; As[0][kq0 + 3][r0l] = av0.w;
        As[0][kq1 + 0][r1l] = av1.x; As[0][kq1 + 1][r1l] = av1.y;
        As[0][kq1 + 2][r1l] = av1.z; As[0][kq1 + 3][r1l] = av1.w;
        Bs[0][kq0 + 0][r0l] = bv0.x; Bs[0][kq0 + 1][r0l] = bv0.y;
        Bs[0][kq0 + 2][r0l] = bv0.z; Bs[0][kq0 + 3][r0l] = bv0.w;
        Bs[0][kq1 + 0][r1l] = bv1.x; Bs[0][kq1 + 1][r1l] = bv1.y;
        Bs[0][kq1 + 2][r1l] = bv1.z; Bs[0][kq1 + 3][r1l] = bv1.w;
    }
    __syncthreads();

    int buf = 0;
    for (int k0 = 0; k0 < K; k0 += GBK) {
        const bool more = (k0 + GBK) < K;
        if (more) {
            const int kn = k0 + GBK;
            av0 = *reinterpret_cast<const float4*>(&X [(size_t)(m0 + r0l) * K + kn + kq0]);
            av1 = *reinterpret_cast<const float4*>(&X [(size_t)(m0 + r1l) * K + kn + kq1]);
            bv0 = *reinterpret_cast<const float4*>(&Wd[(size_t)(n0 + r0l) * K + kn + kq0]);
            bv1 = *reinterpret_cast<const float4*>(&Wd[(size_t)(n0 + r1l) * K + kn + kq1]);
        }

#pragma unroll
        for (int k = 0; k < GBK; k++) {
            float4 a0 = *reinterpret_cast<const float4*>(&As[buf][k][ty * 8]);
            float4 a1 = *reinterpret_cast<const float4*>(&As[buf][k][ty * 8 + 4]);
            const ull* bp = reinterpret_cast<const ull*>(&Bs[buf][k][tx * 8]);
            ull b0 = bp[0], b1 = bp[1], b2 = bp[2], b3 = bp[3];
            float aa[8] = {a0.x, a0.y, a0.z, a0.w, a1.x, a1.y, a1.z, a1.w};
#pragma unroll
            for (int i = 0; i < 8; i++) {
                ull ap = pk2(aa[i], aa[i]);
                acc[i][0] = fma2(ap, b0, acc[i][0]);
                acc[i][1] = fma2(ap, b1, acc[i][1]);
                acc[i][2] = fma2(ap, b2, acc[i][2]);
                acc[i][3] = fma2(ap, b3, acc[i][3]);
            }
        }

        if (more) {
            const int nb = buf ^ 1;
            As[nb][kq0 + 0][r0l] = av0.x; As[nb][kq0 + 1][r0l] = av0.y;
            As[nb][kq0 + 2][r0l] = av0.z; As[nb][kq0 + 3][r0l] = av0.w;
            As[nb][kq1 + 0][r1l] = av1.x; As[nb][kq1 + 1][r1l] = av1.y;
            As[nb][kq1 + 2][r1l] = av1.z; As[nb][kq1 + 3][r1l] = av1.w;
            Bs[nb][kq0 + 0][r0l] = bv0.x; Bs[nb][kq0 + 1][r0l] = bv0.y;
            Bs[nb][kq0 + 2][r0l] = bv0.z; Bs[nb][kq0 + 3][r0l] = bv0.w;
            Bs[nb][kq1 + 0][r1l] = bv1.x; Bs[nb][kq1 + 1][r1l] = bv1.y;
            Bs[nb][kq1 + 2][r1l] = bv1.z; Bs[nb][kq1 + 3][r1l] = bv1.w;
            __syncthreads();
            buf = nb;
        }
    }

    float biasn[8];
#pragma unroll
    for (int q = 0; q < 8; q++) {
        int n = n0 + tx * 8 + q;
        biasn[q] = bi[d * 512 + n] + bh[d * 512 + n];
    }
#pragma unroll
    for (int i = 0; i < 8; i++) {
        int m = m0 + ty * 8 + i;
        float2 v0 = upk2(acc[i][0]);
        float2 v1 = upk2(acc[i][1]);
        float2 v2 = upk2(acc[i][2]);
        float2 v3 = upk2(acc[i][3]);
        float4 o0 = make_float4(v0.x + biasn[0], v0.y + biasn[1],
                                v1.x + biasn[2], v1.y + biasn[3]);
        float4 o1 = make_float4(v2.x + biasn[4], v2.y + biasn[5],
                                v3.x + biasn[6], v3.y + biasn[7]);
        *reinterpret_cast<float4*>(&Cd[(size_t)m * 512 + n0 + tx * 8 + 0]) = o0;
        *reinterpret_cast<float4*>(&Cd[(size_t)m * 512 + n0 + tx * 8 + 4]) = o1;
    }
}

// ---------------------------------------------------------------------------
// Kernel 2b: layer-2 backward last-timestep GEMV
// ---------------------------------------------------------------------------
__global__ __launch_bounds__(256)
void gemv_last(const float* __restrict__ y,
               const float* __restrict__ Wfull,
               const float* __restrict__ bi,
               const float* __restrict__ bh,
               float* __restrict__ out) {
    __shared__ float xr[256];
    const int b = blockIdx.x;
    const float* x = y + ((size_t)b * TT + (TT - 1)) * 256;
    xr[threadIdx.x] = x[threadIdx.x];
    __syncthreads();
#pragma unroll
    for (int nn = 0; nn < 2; nn++) {
        int n = threadIdx.x + nn * 256;
        const float* wr = Wfull + (size_t)(512 + n) * 256;
        ull s2 = 0ull;
        const ull* xp = reinterpret_cast<const ull*>(xr);
        const ull* wp = reinterpret_cast<const ull*>(wr);
#pragma unroll
        for (int k = 0; k < 128; k++) s2 = fma2(xp[k], wp[k], s2);
        out[(size_t)b * 512 + n] = hsum2(s2) + bi[512 + n] + bh[512 + n];
    }
}

// ---------------------------------------------------------------------------
// Kernel 3: LSTM recurrence.
//   tid = j*2 + p  (j = hidden unit, p = k-half). Partner lanes adjacent ->
//   shfl.bfly(1) reduce, ping-pong h buffer, ONE barrier per step.
//   i,f,g weights in registers (96 ull), o-gate streamed from smem.
// ---------------------------------------------------------------------------
#define WO_STRIDE 68
#define WO_FLOATS (256 * WO_STRIDE)
#define HV_OFF    WO_FLOATS
#define LSTM3_SMEM ((WO_FLOATS + 2 * 128 + 32) * 4)

__global__ __launch_bounds__(256, 1)
void lstm3(const float* __restrict__ xg,
           const float* __restrict__ xgB,
           const float* __restrict__ whh,
           const float* __restrict__ hx0,
           const float* __restrict__ cx0,
           float* __restrict__ y,
           int final_layer) {
    extern __shared__ float sm[];
    float* Wo_s = sm;
    float* hvec = sm + HV_OFF;          // [2][128] ping-pong

    const int tid = threadIdx.x;
    const int j   = tid >> 1;
    const int p   = tid & 1;
    const int d   = blockIdx.x >> 6;
    const int b   = blockIdx.x & 63;
    const int kb  = p << 6;

    const float* W = whh + (size_t)d * 512 * 128;

    // one-time: o-gate to smem; thread t=(j,p) owns row Wo[j][p*64 .. p*64+64)
    for (int idx = tid; idx < 128 * 128; idx += 256) {
        int r = idx >> 7, k = idx & 127;
        Wo_s[(r * 2 + (k >> 6)) * WO_STRIDE + (k & 63)] = W[(size_t)(384 + r) * 128 + k];
    }

    // one-time: i,f,g weights into registers as consecutive-k f32x2 pairs
    ull Wi[32], Wf[32], Wg[32];
    {
        const float2* ri = reinterpret_cast<const float2*>(W + (size_t)(0   + j) * 128 + kb);
        const float2* rf = reinterpret_cast<const float2*>(W + (size_t)(128 + j) * 128 + kb);
        const float2* rg = reinterpret_cast<const float2*>(W + (size_t)(256 + j) * 128 + kb);
#pragma unroll
        for (int q = 0; q < 32; q++) {
            float2 a = ri[q]; Wi[q] = pk2(a.x, a.y);
            float2 f = rf[q]; Wf[q] = pk2(f.x, f.y);
            float2 g = rg[q]; Wg[q] = pk2(g.x, g.y);
        }
    }

    float c = cx0[(size_t)(d * 64 + b) * 128 + j];     // both lanes hold copy
    if (p == 0) hvec[j] = hx0[(size_t)(d * 64 + b) * 128 + j];
    __syncthreads();

    const int t0 = d ? (TT - 1) : 0;
    const int dt = d ? -1 : 1;
    const bool bwd_last = (final_layer && d);
    const int nsteps = bwd_last ? 1 : TT;
    const float* xgb = xg + ((size_t)d * MMM + (size_t)b * TT) * 512;

    float xi, xf, xgv, xo;
    {
        const float* row = bwd_last ? (xgB + (size_t)b * 512)
                                    : (xgb + (size_t)t0 * 512);
        xi  = row[j];
        xf  = row[128 + j];
        xgv = row[256 + j];
        xo  = row[384 + j];
    }

    const float* worow = Wo_s + (size_t)tid * WO_STRIDE;

    for (int s = 0; s < nsteps; s++) {
        const int t = t0 + s * dt;
        const int cur = s & 1;
        const float* hbase = hvec + cur * 128 + kb;

        ull aI = 0ull, aF = 0ull, aG = 0ull, aO = 0ull;
#pragma unroll
        for (int q4 = 0; q4 < 16; q4++) {
            ulonglong2 hq = *reinterpret_cast<const ulonglong2*>(hbase + 4 * q4);
            ulonglong2 wq = *reinterpret_cast<const ulonglong2*>(worow + 4 * q4);
            aI = fma2(hq.x, Wi[2 * q4], aI);
            aF = fma2(hq.x, Wf[2 * q4], aF);
            aG = fma2(hq.x, Wg[2 * q4], aG);
            aO = fma2(hq.x, wq.x,       aO);
            aI = fma2(hq.y, Wi[2 * q4 + 1], aI);
            aF = fma2(hq.y, Wf[2 * q4 + 1], aF);
            aG = fma2(hq.y, Wg[2 * q4 + 1], aG);
            aO = fma2(hq.y, wq.y,           aO);
        }

        // pairwise reduce across partner lanes (p=0 / p=1)
        float sI = hsum2(aI); sI += __shfl_xor_sync(0xffffffffu, sI, 1);
        float sF = hsum2(aF); sF += __shfl_xor_sync(0xffffffffu, sF, 1);
        float sG = hsum2(aG); sG += __shfl_xor_sync(0xffffffffu, sG, 1);
        float sO = hsum2(aO); sO += __shfl_xor_sync(0xffffffffu, sO, 1);

        float ai = sI + xi, af = sF + xf, ag = sG + xgv, ao = sO + xo;

        // prefetch next xg while activations run
        if (s + 1 < nsteps) {
            const size_t bse = (size_t)(t + dt) * 512;
            xi  = xgb[bse + j];
            xf  = xgb[bse + 128 + j];
            xgv = xgb[bse + 256 + j];
            xo  = xgb[bse + 384 + j];
        }

        float ig = sig_a(ai);
        float fg = sig_a(af);
        float og = sig_a(ao);
        c = fmaf(fg, c, ig * tanh_a(ag));
        float hn = og * tanh_a(c);

        if (p == 0) {
            hvec[(cur ^ 1) * 128 + j] = hn;
            if (!final_layer) {
                y[((size_t)b * TT + t) * 256 + d * 128 + j] = hn;
            } else if (s == nsteps - 1) {
                y[(size_t)b * 256 + d * 128 + j] = hn;
            }
        }
        __syncthreads();
    }
}

// ---------------------------------------------------------------------------
// Kernel 4: linear head
// ---------------------------------------------------------------------------
__global__ void head_k(const float* __restrict__ ylast,
                       const float* __restrict__ w,
                       const float* __restrict__ bsc,
                       float* __restrict__ out) {
    int b = blockIdx.x;
    int l = threadIdx.x;
    float s = 0.f;
#pragma unroll
    for (int k = l; k < 256; k += 32) s += ylast[(size_t)b * 256 + k] * w[k];
#pragma unroll
    for (int o = 16; o; o >>= 1) s += __shfl_xor_sync(0xffffffffu, s, o);
    if (l == 0) out[b] = s + bsc[0];
}

// ---------------------------------------------------------------------------
extern "C" void kernel_launch(void* const* d_in, const int* in_sizes, int n_in,
                              void* d_out, int out_size) {
    const int*   X     = (const int*)d_in[0];
    const float* emb   = (const float*)d_in[1];
    const float* hx    = (const float*)d_in[2];
    const float* cx    = (const float*)d_in[3];
    const float* lin_w = (const float*)d_in[4];
    const float* lin_b = (const float*)d_in[5];
    const float* w_ih[3] = {(const float*)d_in[6],  (const float*)d_in[10], (const float*)d_in[14]};
    const float* w_hh[3] = {(const float*)d_in[7],  (const float*)d_in[11], (const float*)d_in[15]};
    const float* b_ih[3] = {(const float*)d_in[8],  (const float*)d_in[12], (const float*)d_in[16]};
    const float* b_hh[3] = {(const float*)d_in[9],  (const float*)d_in[13], (const float*)d_in[17]};
    float* out = (float*)d_out;

    float *x0, *xgp, *xgB, *ya, *yb, *ylast;
    cudaGetSymbolAddress((void**)&x0,    g_x0);
    cudaGetSymbolAddress((void**)&xgp,   g_xg);
    cudaGetSymbolAddress((void**)&xgB,   g_xgB);
    cudaGetSymbolAddress((void**)&ya,    g_ya);
    cudaGetSymbolAddress((void**)&yb,    g_yb);
    cudaGetSymbolAddress((void**)&ylast, g_ylast);

    cudaFuncSetAttribute(lstm3,
                         cudaFuncAttributeMaxDynamicSharedMemorySize, LSTM3_SMEM);

    embed_k<<<(MMM * 32) / 256, 256>>>(X, emb, x0);

    gemm_xw<<<dim3(512 / GBN, MMM / GBM, 2), 256>>>(x0, w_ih[0], b_ih[0], b_hh[0], xgp, 128);
    lstm3<<<128, 256, LSTM3_SMEM>>>(xgp, nullptr, w_hh[0], hx + 0 * BB * 128, cx + 0 * BB * 128, ya, 0);

    gemm_xw<<<dim3(512 / GBN, MMM / GBM, 2), 256>>>(ya, w_ih[1], b_ih[1], b_hh[1], xgp, 256);
    lstm3<<<128, 256, LSTM3_SMEM>>>(xgp, nullptr, w_hh[1], hx + 2 * BB * 128, cx + 2 * BB * 128, yb, 0);

    gemm_xw<<<dim3(512 / GBN, MMM / GBM, 1), 256>>>(yb, w_ih[2], b_ih[2], b_hh[2], xgp, 256);
    gemv_last<<<BB, 256>>>(yb, w_ih[2], b_ih[2], b_hh[2], xgB);
    lstm3<<<128, 256, LSTM3_SMEM>>>(xgp, xgB, w_hh[2], hx + 4 * BB * 128, cx + 4 * BB * 128, ylast, 1);

    head_k<<<BB, 32>>>(ylast, lin_w, lin_b, out);
}

// round 10
// speedup vs baseline: 1.1164x; 1.1164x over previous
#include <cuda_runtime.h>
#include <cuda_bf16.h>

typedef unsigned long long ull;

#define BB    64
#define TT    512
#define MMM   (BB * TT)

__device__ float g_x0[MMM * 128];
__device__ float g_xg[2u * MMM * 512];
__device__ float g_xgB[BB * 512];
__device__ float g_ya[MMM * 256];
__device__ float g_yb[MMM * 256];
__device__ float g_ylast[BB * 256];

// ---------------------------------------------------------------------------
__device__ __forceinline__ ull pk2(float lo, float hi) {
    ull r; asm("mov.b64 %0, {%1, %2};" : "=l"(r) : "f"(lo), "f"(hi)); return r;
}
__device__ __forceinline__ ull fma2(ull a, ull b, ull c) {
    ull d; asm("fma.rn.f32x2 %0, %1, %2, %3;" : "=l"(d) : "l"(a), "l"(b), "l"(c)); return d;
}
__device__ __forceinline__ ull add2(ull a, ull b) {
    ull d; asm("add.rn.f32x2 %0, %1, %2;" : "=l"(d) : "l"(a), "l"(b)); return d;
}
__device__ __forceinline__ float2 upk2(ull v) {
    float2 f; asm("mov.b64 {%0, %1}, %2;" : "=f"(f.x), "=f"(f.y) : "l"(v)); return f;
}
__device__ __forceinline__ float hsum2(ull v) { float2 f = upk2(v); return f.x + f.y; }

__device__ __forceinline__ float tanh_a(float x) {
    float r; asm("tanh.approx.f32 %0, %1;" : "=f"(r) : "f"(x)); return r;
}
__device__ __forceinline__ float sig_a(float x) {
    return fmaf(0.5f, tanh_a(0.5f * x), 0.5f);
}

// ---------------------------------------------------------------------------
// Kernel 1: embedding gather
// ---------------------------------------------------------------------------
__global__ void embed_k(const int* __restrict__ X,
                        const float* __restrict__ emb,
                        float* __restrict__ out) {
    int i = blockIdx.x * blockDim.x + threadIdx.x;
    int m  = i >> 5;
    int e4 = (i & 31) << 2;
    int v  = X[m];
    *reinterpret_cast<float4*>(&out[(size_t)m * 128 + e4]) =
        *reinterpret_cast<const float4*>(&emb[(size_t)v * 128 + e4]);
}

// ---------------------------------------------------------------------------
// Kernel 2: input GEMM (A-broadcast lane map: tx=tid&15 -> n, ty=tid>>4 -> m)
//   Thread n-columns: {4tx..4tx+3} U {64+4tx..64+4tx+3}  -> B reads are two
//   contiguous-256B LDS.128 (2 wf each). Loader: 1 row per thread.
// ---------------------------------------------------------------------------
#define GBM 128
#define GBN 128
#define GBK 16

__global__ __launch_bounds__(256, 2)
void gemm_xw(const float* __restrict__ X,
             const float* __restrict__ Wfull,
             const float* __restrict__ bi,
             const float* __restrict__ bh,
             float* __restrict__ C,
             int K) {
    const int d  = blockIdx.z;
    const float* Wd = Wfull + (size_t)d * 512 * K;
    float* Cd       = C     + (size_t)d * MMM * 512;

    __shared__ float As[2][GBK][GBM];
    __shared__ float Bs[2][GBK][GBN];

    const int m0 = blockIdx.y * GBM;
    const int n0 = blockIdx.x * GBN;
    const int tid = threadIdx.x;
    const int tx = tid & 15;        // n chunk selector
    const int ty = tid >> 4;        // m block (A broadcast within half-warp)

    const int rowL = tid & 127;
    const int kqL  = (tid >> 7) << 2;      // 0 or 4

    ull acc[8][4];
#pragma unroll
    for (int i = 0; i < 8; i++)
#pragma unroll
        for (int jp = 0; jp < 4; jp++) acc[i][jp] = 0ull;

    float4 av0 = *reinterpret_cast<const float4*>(&X [(size_t)(m0 + rowL) * K + kqL]);
    float4 av1 = *reinterpret_cast<const float4*>(&X [(size_t)(m0 + rowL) * K + kqL + 8]);
    float4 bv0 = *reinterpret_cast<const float4*>(&Wd[(size_t)(n0 + rowL) * K + kqL]);
    float4 bv1 = *reinterpret_cast<const float4*>(&Wd[(size_t)(n0 + rowL) * K + kqL + 8]);
    {
        As[0][kqL + 0][rowL] = av0.x; As[0][kqL + 1][rowL] = av0.y;
        As[0][kqL + 2][rowL] = av0.z; As[0][kqL + 3][rowL] = av0.w;
        As[0][kqL + 8][rowL] = av1.x; As[0][kqL + 9][rowL] = av1.y;
        As[0][kqL +10][rowL] = av1.z; As[0][kqL +11][rowL] = av1.w;
        Bs[0][kqL + 0][rowL] = bv0.x; Bs[0][kqL + 1][rowL] = bv0.y;
        Bs[0][kqL + 2][rowL] = bv0.z; Bs[0][kqL + 3][rowL] = bv0.w;
        Bs[0][kqL + 8][rowL] = bv1.x; Bs[0][kqL + 9][rowL] = bv1.y;
        Bs[0][kqL +10][rowL] = bv1.z; Bs[0][kqL +11][rowL] = bv1.w;
    }
    __syncthreads();

    int buf = 0;
    for (int k0 = 0; k0 < K; k0 += GBK) {
        const bool more = (k0 + GBK) < K;
        if (more) {
            const int kn = k0 + GBK;
            av0 = *reinterpret_cast<const float4*>(&X [(size_t)(m0 + rowL) * K + kn + kqL]);
            av1 = *reinterpret_cast<const float4*>(&X [(size_t)(m0 + rowL) * K + kn + kqL + 8]);
            bv0 = *reinterpret_cast<const float4*>(&Wd[(size_t)(n0 + rowL) * K + kn + kqL]);
            bv1 = *reinterpret_cast<const float4*>(&Wd[(size_t)(n0 + rowL) * K + kn + kqL + 8]);
        }

#pragma unroll
        for (int k = 0; k < GBK; k++) {
            float4 a0 = *reinterpret_cast<const float4*>(&As[buf][k][ty * 8]);
            float4 a1 = *reinterpret_cast<const float4*>(&As[buf][k][ty * 8 + 4]);
            ulonglong2 bq0 = *reinterpret_cast<const ulonglong2*>(&Bs[buf][k][tx * 4]);
            ulonglong2 bq1 = *reinterpret_cast<const ulonglong2*>(&Bs[buf][k][64 + tx * 4]);
            float aa[8] = {a0.x, a0.y, a0.z, a0.w, a1.x, a1.y, a1.z, a1.w};
#pragma unroll
            for (int i = 0; i < 8; i++) {
                ull ap = pk2(aa[i], aa[i]);
                acc[i][0] = fma2(ap, bq0.x, acc[i][0]);
                acc[i][1] = fma2(ap, bq0.y, acc[i][1]);
                acc[i][2] = fma2(ap, bq1.x, acc[i][2]);
                acc[i][3] = fma2(ap, bq1.y, acc[i][3]);
            }
        }

        if (more) {
            const int nb = buf ^ 1;
            As[nb][kqL + 0][rowL] = av0.x; As[nb][kqL + 1][rowL] = av0.y;
            As[nb][kqL + 2][rowL] = av0.z; As[nb][kqL + 3][rowL] = av0.w;
            As[nb][kqL + 8][rowL] = av1.x; As[nb][kqL + 9][rowL] = av1.y;
            As[nb][kqL +10][rowL] = av1.z; As[nb][kqL +11][rowL] = av1.w;
            Bs[nb][kqL + 0][rowL] = bv0.x; Bs[nb][kqL + 1][rowL] = bv0.y;
            Bs[nb][kqL + 2][rowL] = bv0.z; Bs[nb][kqL + 3][rowL] = bv0.w;
            Bs[nb][kqL + 8][rowL] = bv1.x; Bs[nb][kqL + 9][rowL] = bv1.y;
            Bs[nb][kqL +10][rowL] = bv1.z; Bs[nb][kqL +11][rowL] = bv1.w;
            __syncthreads();
            buf = nb;
        }
    }

    const int nA = n0 + tx * 4;
    const int nB = n0 + 64 + tx * 4;
    float biasA[4], biasB[4];
#pragma unroll
    for (int q = 0; q < 4; q++) {
        biasA[q] = bi[d * 512 + nA + q] + bh[d * 512 + nA + q];
        biasB[q] = bi[d * 512 + nB + q] + bh[d * 512 + nB + q];
    }
#pragma unroll
    for (int i = 0; i < 8; i++) {
        int m = m0 + ty * 8 + i;
        float2 v0 = upk2(acc[i][0]);
        float2 v1 = upk2(acc[i][1]);
        float2 v2 = upk2(acc[i][2]);
        float2 v3 = upk2(acc[i][3]);
        float4 oA = make_float4(v0.x + biasA[0], v0.y + biasA[1],
                                v1.x + biasA[2], v1.y + biasA[3]);
        float4 oB = make_float4(v2.x + biasB[0], v2.y + biasB[1],
                                v3.x + biasB[2], v3.y + biasB[3]);
        *reinterpret_cast<float4*>(&Cd[(size_t)m * 512 + nA]) = oA;
        *reinterpret_cast<float4*>(&Cd[(size_t)m * 512 + nB]) = oB;
    }
}

// ---------------------------------------------------------------------------
// Kernel 2b: layer-2 backward last-timestep GEMV
// ---------------------------------------------------------------------------
__global__ __launch_bounds__(256)
void gemv_last(const float* __restrict__ y,
               const float* __restrict__ Wfull,
               const float* __restrict__ bi,
               const float* __restrict__ bh,
               float* __restrict__ out) {
    __shared__ float xr[256];
    const int b = blockIdx.x;
    const float* x = y + ((size_t)b * TT + (TT - 1)) * 256;
    xr[threadIdx.x] = x[threadIdx.x];
    __syncthreads();
#pragma unroll
    for (int nn = 0; nn < 2; nn++) {
        int n = threadIdx.x + nn * 256;
        const float* wr = Wfull + (size_t)(512 + n) * 256;
        ull s2 = 0ull;
        const ull* xp = reinterpret_cast<const ull*>(xr);
        const ull* wp = reinterpret_cast<const ull*>(wr);
#pragma unroll
        for (int k = 0; k < 128; k++) s2 = fma2(xp[k], wp[k], s2);
        out[(size_t)b * 512 + n] = hsum2(s2) + bi[512 + n] + bh[512 + n];
    }
}

// ---------------------------------------------------------------------------
// Kernel 3: LSTM recurrence (smem reduce, tid = p*128 + j).
//   i,f,g gate weights in registers (96 ull), o gate streamed from smem.
//   Activations via tanh.approx.
// ---------------------------------------------------------------------------
#define WO_STRIDE 68
#define WO_FLOATS (256 * WO_STRIDE)
#define RED_OFF   WO_FLOATS
#define HV_OFF    (WO_FLOATS + 2048)
#define LSTM2_SMEM ((HV_OFF + 160) * 4)

__global__ __launch_bounds__(256, 1)
void lstm2(const float* __restrict__ xg,
           const float* __restrict__ xgB,
           const float* __restrict__ whh,
           const float* __restrict__ hx0,
           const float* __restrict__ cx0,
           float* __restrict__ y,
           int final_layer) {
    extern __shared__ float sm[];
    float* Wo_s = sm;
    ull*   red  = reinterpret_cast<ull*>(sm + RED_OFF);
    float* hvec = sm + HV_OFF;

    const int tid = threadIdx.x;
    const int j   = tid & 127;
    const int p   = tid >> 7;
    const int d   = blockIdx.x >> 6;
    const int b   = blockIdx.x & 63;
    const int kb  = p << 6;

    const float* W = whh + (size_t)d * 512 * 128;

    for (int idx = tid; idx < 128 * 128; idx += 256) {
        int r = idx >> 7, k = idx & 127;
        float v = W[(size_t)(384 + r) * 128 + k];
        Wo_s[((k >> 6) * 128 + r) * WO_STRIDE + (k & 63)] = v;
    }

    ull Wi[32], Wf[32], Wg[32];
    {
        const float2* ri = reinterpret_cast<const float2*>(W + (size_t)(0   + j) * 128 + kb);
        const float2* rf = reinterpret_cast<const float2*>(W + (size_t)(128 + j) * 128 + kb);
        const float2* rg = reinterpret_cast<const float2*>(W + (size_t)(256 + j) * 128 + kb);
#pragma unroll
        for (int q = 0; q < 32; q++) {
            float2 a = ri[q]; Wi[q] = pk2(a.x, a.y);
            float2 f = rf[q]; Wf[q] = pk2(f.x, f.y);
            float2 g = rg[q]; Wg[q] = pk2(g.x, g.y);
        }
    }

    float c = cx0[(size_t)(d * 64 + b) * 128 + j];
    if (tid < 128) hvec[tid] = hx0[(size_t)(d * 64 + b) * 128 + tid];
    __syncthreads();

    const int t0 = d ? (TT - 1) : 0;
    const int dt = d ? -1 : 1;
    const bool bwd_last = (final_layer && d);
    const int nsteps = bwd_last ? 1 : TT;
    const float* xgb = xg + ((size_t)d * MMM + (size_t)b * TT) * 512;

    float xi = 0.f, xf = 0.f, xgv = 0.f, xo = 0.f;
    if (p == 0) {
        const float* row = bwd_last ? (xgB + (size_t)b * 512)
                                    : (xgb + (size_t)t0 * 512);
        xi  = row[j];
        xf  = row[128 + j];
        xgv = row[256 + j];
        xo  = row[384 + j];
    }

    const float* worow = Wo_s + (size_t)tid * WO_STRIDE;
    const float* hbase = hvec + kb;

    for (int s = 0; s < nsteps; s++) {
        const int t = t0 + s * dt;

        ull aI = 0ull, aF = 0ull, aG = 0ull, aO = 0ull;
#pragma unroll
        for (int q4 = 0; q4 < 16; q4++) {
            ulonglong2 hq = *reinterpret_cast<const ulonglong2*>(hbase + 4 * q4);
            ulonglong2 wq = *reinterpret_cast<const ulonglong2*>(worow + 4 * q4);
            aI = fma2(hq.x, Wi[2 * q4], aI);
            aF = fma2(hq.x, Wf[2 * q4], aF);
            aG = fma2(hq.x, Wg[2 * q4], aG);
            aO = fma2(hq.x, wq.x,       aO);
            aI = fma2(hq.y, Wi[2 * q4 + 1], aI);
            aF = fma2(hq.y, Wf[2 * q4 + 1], aF);
            aG = fma2(hq.y, Wg[2 * q4 + 1], aG);
            aO = fma2(hq.y, wq.y,           aO);
        }
        red[0 * 256 + tid] = aI;
        red[1 * 256 + tid] = aF;
        red[2 * 256 + tid] = aG;
        red[3 * 256 + tid] = aO;
        __syncthreads();

        float nxi = 0.f, nxf = 0.f, nxg = 0.f, nxo = 0.f;
        if (p == 0 && s + 1 < nsteps) {
            const size_t bse = (size_t)(t + dt) * 512;
            nxi = xgb[bse + j];
            nxf = xgb[bse + 128 + j];
            nxg = xgb[bse + 256 + j];
            nxo = xgb[bse + 384 + j];
        }

        if (p == 0) {
            float ai = hsum2(add2(red[0 * 256 + j], red[0 * 256 + 128 + j])) + xi;
            float af = hsum2(add2(red[1 * 256 + j], red[1 * 256 + 128 + j])) + xf;
            float ag = hsum2(add2(red[2 * 256 + j], red[2 * 256 + 128 + j])) + xgv;
            float ao = hsum2(add2(red[3 * 256 + j], red[3 * 256 + 128 + j])) + xo;

            float ig = sig_a(ai);
            float fg = sig_a(af);
            float og = sig_a(ao);
            c = fmaf(fg, c, ig * tanh_a(ag));
            float hn = og * tanh_a(c);

            hvec[j] = hn;
            if (!final_layer) {
                y[((size_t)b * TT + t) * 256 + d * 128 + j] = hn;
            } else if (s == nsteps - 1) {
                y[(size_t)b * 256 + d * 128 + j] = hn;
            }
        }
        __syncthreads();

        xi = nxi; xf = nxf; xgv = nxg; xo = nxo;
    }
}

// ---------------------------------------------------------------------------
// Kernel 4: linear head
// ---------------------------------------------------------------------------
__global__ void head_k(const float* __restrict__ ylast,
                       const float* __restrict__ w,
                       const float* __restrict__ bsc,
                       float* __restrict__ out) {
    int b = blockIdx.x;
    int l = threadIdx.x;
    float s = 0.f;
#pragma unroll
    for (int k = l; k < 256; k += 32) s += ylast[(size_t)b * 256 + k] * w[k];
#pragma unroll
    for (int o = 16; o; o >>= 1) s += __shfl_xor_sync(0xffffffffu, s, o);
    if (l == 0) out[b] = s + bsc[0];
}

// ---------------------------------------------------------------------------
extern "C" void kernel_launch(void* const* d_in, const int* in_sizes, int n_in,
                              void* d_out, int out_size) {
    const int*   X     = (const int*)d_in[0];
    const float* emb   = (const float*)d_in[1];
    const float* hx    = (const float*)d_in[2];
    const float* cx    = (const float*)d_in[3];
    const float* lin_w = (const float*)d_in[4];
    const float* lin_b = (const float*)d_in[5];
    const float* w_ih[3] = {(const float*)d_in[6],  (const float*)d_in[10], (const float*)d_in[14]};
    const float* w_hh[3] = {(const float*)d_in[7],  (const float*)d_in[11], (const float*)d_in[15]};
    const float* b_ih[3] = {(const float*)d_in[8],  (const float*)d_in[12], (const float*)d_in[16]};
    const float* b_hh[3] = {(const float*)d_in[9],  (const float*)d_in[13], (const float*)d_in[17]};
    float* out = (float*)d_out;

    float *x0, *xgp, *xgB, *ya, *yb, *ylast;
    cudaGetSymbolAddress((void**)&x0,    g_x0);
    cudaGetSymbolAddress((void**)&xgp,   g_xg);
    cudaGetSymbolAddress((void**)&xgB,   g_xgB);
    cudaGetSymbolAddress((void**)&ya,    g_ya);
    cudaGetSymbolAddress((void**)&yb,    g_yb);
    cudaGetSymbolAddress((void**)&ylast, g_ylast);

    cudaFuncSetAttribute(lstm2,
                         cudaFuncAttributeMaxDynamicSharedMemorySize, LSTM2_SMEM);

    embed_k<<<(MMM * 32) / 256, 256>>>(X, emb, x0);

    gemm_xw<<<dim3(512 / GBN, MMM / GBM, 2), 256>>>(x0, w_ih[0], b_ih[0], b_hh[0], xgp, 128);
    lstm2<<<128, 256, LSTM2_SMEM>>>(xgp, nullptr, w_hh[0], hx + 0 * BB * 128, cx + 0 * BB * 128, ya, 0);

    gemm_xw<<<dim3(512 / GBN, MMM / GBM, 2), 256>>>(ya, w_ih[1], b_ih[1], b_hh[1], xgp, 256);
    lstm2<<<128, 256, LSTM2_SMEM>>>(xgp, nullptr, w_hh[1], hx + 2 * BB * 128, cx + 2 * BB * 128, yb, 0);

    gemm_xw<<<dim3(512 / GBN, MMM / GBM, 1), 256>>>(yb, w_ih[2], b_ih[2], b_hh[2], xgp, 256);
    gemv_last<<<BB, 256>>>(yb, w_ih[2], b_ih[2], b_hh[2], xgB);
    lstm2<<<128, 256, LSTM2_SMEM>>>(xgp, xgB, w_hh[2], hx + 4 * BB * 128, cx + 4 * BB * 128, ylast, 1);

    head_k<<<BB, 32>>>(ylast, lin_w, lin_b, out);
}

// round 13
// speedup vs baseline: 1.2755x; 1.1425x over previous
#include <cuda_runtime.h>
#include <cuda_bf16.h>
#include <cstdint>

typedef unsigned long long ull;

#define BB    64
#define TT    512
#define MMM   (BB * TT)

// ---------------------------------------------------------------------------
// Scratch (static __device__ arrays -- allocation-free)
// ---------------------------------------------------------------------------
__device__ float g_x0[MMM * 128];
__device__ float g_xg[2u * MMM * 512];
__device__ float g_xgB[BB * 512];
__device__ float g_ya[MMM * 256];
__device__ float g_yb[MMM * 256];
__device__ float g_ylast[BB * 256];
__device__ __nv_bfloat16 g_xc[(size_t)MMM * 768];   // split X  [M][3K]
__device__ __nv_bfloat16 g_wc[1024 * 768];          // split W  [N][3K]
__device__ float g_bias[1024];

// ---------------------------------------------------------------------------
// f32x2 helpers (LSTM / gemv)
// ---------------------------------------------------------------------------
__device__ __forceinline__ ull pk2(float lo, float hi) {
    ull r; asm("mov.b64 %0, {%1, %2};" : "=l"(r) : "f"(lo), "f"(hi)); return r;
}
__device__ __forceinline__ ull fma2(ull a, ull b, ull c) {
    ull d; asm("fma.rn.f32x2 %0, %1, %2, %3;" : "=l"(d) : "l"(a), "l"(b), "l"(c)); return d;
}
__device__ __forceinline__ ull add2(ull a, ull b) {
    ull d; asm("add.rn.f32x2 %0, %1, %2;" : "=l"(d) : "l"(a), "l"(b)); return d;
}
__device__ __forceinline__ float2 upk2(ull v) {
    float2 f; asm("mov.b64 {%0, %1}, %2;" : "=f"(f.x), "=f"(f.y) : "l"(v)); return f;
}
__device__ __forceinline__ float hsum2(ull v) { float2 f = upk2(v); return f.x + f.y; }

__device__ __forceinline__ float tanh_a(float x) {
    float r; asm("tanh.approx.f32 %0, %1;" : "=f"(r) : "f"(x)); return r;
}
__device__ __forceinline__ float sig_a(float x) {
    return fmaf(0.5f, tanh_a(0.5f * x), 0.5f);
}

__device__ __forceinline__ uint32_t smem_u32(const void* p) {
    uint32_t a;
    asm("{ .reg .u64 t; cvta.to.shared.u64 t, %1; cvt.u32.u64 %0, t; }" : "=r"(a) : "l"(p));
    return a;
}

// ---------------------------------------------------------------------------
// Kernel 1: embedding gather
// ---------------------------------------------------------------------------
__global__ void embed_k(const int* __restrict__ X,
                        const float* __restrict__ emb,
                        float* __restrict__ out) {
    int i = blockIdx.x * blockDim.x + threadIdx.x;
    int m  = i >> 5;
    int e4 = (i & 31) << 2;
    int v  = X[m];
    *reinterpret_cast<float4*>(&out[(size_t)m * 128 + e4]) =
        *reinterpret_cast<const float4*>(&emb[(size_t)v * 128 + e4]);
}

// ---------------------------------------------------------------------------
// Conversions: fp32 [R][K] -> bf16 split [R][3K]
//   X: [hi | hi | lo]     W: [hi | lo | hi]
// ---------------------------------------------------------------------------
__global__ void conv_x(const float* __restrict__ in, __nv_bfloat16* __restrict__ out,
                       int kshift) {
    int i = blockIdx.x * 256 + threadIdx.x;
    int K = 1 << kshift;
    int m = i >> kshift;
    int k = i & (K - 1);
    float v = in[i];
    __nv_bfloat16 hi = __float2bfloat16(v);
    __nv_bfloat16 lo = __float2bfloat16(v - __bfloat162float(hi));
    size_t base = (size_t)m * 3 * K;
    out[base + k]         = hi;
    out[base + K + k]     = hi;
    out[base + 2 * K + k] = lo;
}

__global__ void conv_w(const float* __restrict__ in, __nv_bfloat16* __restrict__ out,
                       int kshift) {
    int i = blockIdx.x * 256 + threadIdx.x;
    int K = 1 << kshift;
    int n = i >> kshift;
    int k = i & (K - 1);
    float v = in[i];
    __nv_bfloat16 hi = __float2bfloat16(v);
    __nv_bfloat16 lo = __float2bfloat16(v - __bfloat162float(hi));
    size_t base = (size_t)n * 3 * K;
    out[base + k]         = hi;
    out[base + K + k]     = lo;
    out[base + 2 * K + k] = hi;
}

__global__ void bias_k(const float* __restrict__ bi, const float* __restrict__ bh,
                       float* __restrict__ out) {
    int i = blockIdx.x * 256 + threadIdx.x;
    out[i] = bi[i] + bh[i];
}

// ---------------------------------------------------------------------------
// Kernel 2: tensor-core GEMM via mma.sync (bf16 -> f32), baseline PTX.
//   C[n>>9][m][n&511] = sum_k' Xc[m][k'] * Wc[n][k'] + bias[n]
//   CTA 128x128, 8 warps (2m x 4n), warp tile 64x32, K-chunk 32,
//   double-buffered smem (80B-padded rows -> conflict-free ldmatrix).
// ---------------------------------------------------------------------------
#define TILE_BYTES 10240   /* 128 rows x 80 B */

#define LDSM4(r0, r1, r2, r3, addr) \
    asm volatile("ldmatrix.sync.aligned.m8n8.x4.shared.b16 {%0,%1,%2,%3}, [%4];" \
        : "=r"(r0), "=r"(r1), "=r"(r2), "=r"(r3) : "r"(addr))

#define MMA16816(d, a, b0, b1) \
    asm volatile("mma.sync.aligned.m16n8k16.row.col.f32.bf16.bf16.f32 " \
        "{%0,%1,%2,%3}, {%4,%5,%6,%7}, {%8,%9}, {%0,%1,%2,%3};" \
        : "+f"((d)[0]), "+f"((d)[1]), "+f"((d)[2]), "+f"((d)[3]) \
        : "r"((a)[0]), "r"((a)[1]), "r"((a)[2]), "r"((a)[3]), "r"(b0), "r"(b1))

__global__ __launch_bounds__(256, 2)
void gemm_mma(const __nv_bfloat16* __restrict__ Xc,
              const __nv_bfloat16* __restrict__ Wc,
              const float* __restrict__ bias,
              float* __restrict__ C,
              int K3, int NC) {
    __shared__ __align__(16) char smA[2][TILE_BYTES];
    __shared__ __align__(16) char smB[2][TILE_BYTES];

    const int tid = threadIdx.x;
    const int w  = tid >> 5, L = tid & 31;
    const int wm = w >> 2,  wn = w & 3;
    const int g  = L >> 3,  r  = L & 7;
    const int m0 = blockIdx.y * 128, n0 = blockIdx.x * 128;

    const uint32_t aSB = smem_u32(smA);
    const uint32_t bSB = smem_u32(smB);

    // ldmatrix per-thread byte offsets
    uint32_t aoff[4][2], boff[2][2];
#pragma unroll
    for (int i = 0; i < 4; i++)
#pragma unroll
        for (int h = 0; h < 2; h++)
            aoff[i][h] = (uint32_t)((wm * 64 + i * 16 + (g & 1) * 8 + r) * 80
                                    + (g >> 1) * 16 + h * 32);
#pragma unroll
    for (int jj = 0; jj < 2; jj++)
#pragma unroll
        for (int h = 0; h < 2; h++)
            boff[jj][h] = (uint32_t)((wn * 32 + jj * 16 + (g >> 1) * 8 + r) * 80
                                     + (g & 1) * 16 + h * 32);

    // loader: 512 16B slots per tile, 2 per thread
    const int s0 = tid * 2, s1 = tid * 2 + 1;
    const int row0 = s0 >> 2, u0 = s0 & 3;
    const int row1 = s1 >> 2, u1 = s1 & 3;

    float acc[16][4];
#pragma unroll
    for (int i = 0; i < 16; i++)
#pragma unroll
        for (int q = 0; q < 4; q++) acc[i][q] = 0.f;

    uint4 ar0, ar1, br0, br1;

#define LDG_CHUNK(c)                                                            \
    {                                                                           \
        ar0 = *reinterpret_cast<const uint4*>(Xc + (size_t)(m0 + row0) * K3 + (c) * 32 + u0 * 8); \
        ar1 = *reinterpret_cast<const uint4*>(Xc + (size_t)(m0 + row1) * K3 + (c) * 32 + u1 * 8); \
        br0 = *reinterpret_cast<const uint4*>(Wc + (size_t)(n0 + row0) * K3 + (c) * 32 + u0 * 8); \
        br1 = *reinterpret_cast<const uint4*>(Wc + (size_t)(n0 + row1) * K3 + (c) * 32 + u1 * 8); \
    }

#define STS_CHUNK(b)                                                            \
    {                                                                           \
        *reinterpret_cast<uint4*>(smA[b] + row0 * 80 + u0 * 16) = ar0;          \
        *reinterpret_cast<uint4*>(smA[b] + row1 * 80 + u1 * 16) = ar1;          \
        *reinterpret_cast<uint4*>(smB[b] + row0 * 80 + u0 * 16) = br0;          \
        *reinterpret_cast<uint4*>(smB[b] + row1 * 80 + u1 * 16) = br1;          \
    }

    LDG_CHUNK(0);
    STS_CHUNK(0);
    __syncthreads();
    if (NC > 1) LDG_CHUNK(1);

    for (int c = 0; c < NC; c++) {
        const int b = c & 1;
        const uint32_t aB = aSB + b * TILE_BYTES;
        const uint32_t bO = bSB + b * TILE_BYTES;
#pragma unroll
        for (int h = 0; h < 2; h++) {
            uint32_t af[4][4], bf2[2][4];
#pragma unroll
            for (int i = 0; i < 4; i++)
                LDSM4(af[i][0], af[i][1], af[i][2], af[i][3], aB + aoff[i][h]);
#pragma unroll
            for (int jj = 0; jj < 2; jj++)
                LDSM4(bf2[jj][0], bf2[jj][1], bf2[jj][2], bf2[jj][3], bO + boff[jj][h]);
#pragma unroll
            for (int i = 0; i < 4; i++) {
#pragma unroll
                for (int nj = 0; nj < 4; nj++) {
                    MMA16816(acc[i * 4 + nj], af[i],
                             bf2[nj >> 1][(nj & 1) * 2], bf2[nj >> 1][(nj & 1) * 2 + 1]);
                }
            }
        }
        if (c + 1 < NC) {
            STS_CHUNK((c + 1) & 1);
            if (c + 2 < NC) LDG_CHUNK(c + 2);
            __syncthreads();
        }
    }

    // epilogue: direct float2 stores + bias
#pragma unroll
    for (int i = 0; i < 4; i++) {
#pragma unroll
        for (int nj = 0; nj < 4; nj++) {
            const int mg = m0 + wm * 64 + i * 16 + (L >> 2);
            const int ng = n0 + wn * 32 + nj * 8 + (L & 3) * 2;
            const int dd = ng >> 9;
            const int col = ng & 511;
            const float bv0 = bias[ng], bv1 = bias[ng + 1];
            float* Cd = C + (size_t)dd * MMM * 512;
            float* p0 = &Cd[(size_t)mg * 512 + col];
            float* p1 = &Cd[(size_t)(mg + 8) * 512 + col];
            *reinterpret_cast<float2*>(p0) =
                make_float2(acc[i * 4 + nj][0] + bv0, acc[i * 4 + nj][1] + bv1);
            *reinterpret_cast<float2*>(p1) =
                make_float2(acc[i * 4 + nj][2] + bv0, acc[i * 4 + nj][3] + bv1);
        }
    }
}

// ---------------------------------------------------------------------------
// Kernel 2b: layer-2 backward last-timestep GEMV (fp32, exact)
// ---------------------------------------------------------------------------
__global__ __launch_bounds__(256)
void gemv_last(const float* __restrict__ y,
               const float* __restrict__ Wfull,
               const float* __restrict__ bi,
               const float* __restrict__ bh,
               float* __restrict__ out) {
    __shared__ float xr[256];
    const int b = blockIdx.x;
    const float* x = y + ((size_t)b * TT + (TT - 1)) * 256;
    xr[threadIdx.x] = x[threadIdx.x];
    __syncthreads();
#pragma unroll
    for (int nn = 0; nn < 2; nn++) {
        int n = threadIdx.x + nn * 256;
        const float* wr = Wfull + (size_t)(512 + n) * 256;
        ull s2 = 0ull;
        const ull* xp = reinterpret_cast<const ull*>(xr);
        const ull* wp = reinterpret_cast<const ull*>(wr);
#pragma unroll
        for (int k = 0; k < 128; k++) s2 = fma2(xp[k], wp[k], s2);
        out[(size_t)b * 512 + n] = hsum2(s2) + bi[512 + n] + bh[512 + n];
    }
}

// ---------------------------------------------------------------------------
// Kernel 3: LSTM recurrence (unchanged from best-passing version).
// ---------------------------------------------------------------------------
#define WO_STRIDE 68
#define WO_FLOATS (256 * WO_STRIDE)
#define RED_OFF   WO_FLOATS
#define HV_OFF    (WO_FLOATS + 2048)
#define LSTM2_SMEM ((HV_OFF + 160) * 4)

__global__ __launch_bounds__(256, 1)
void lstm2(const float* __restrict__ xg,
           const float* __restrict__ xgB,
           const float* __restrict__ whh,
           const float* __restrict__ hx0,
           const float* __restrict__ cx0,
           float* __restrict__ y,
           int final_layer) {
    extern __shared__ float sm[];
    float* Wo_s = sm;
    ull*   red  = reinterpret_cast<ull*>(sm + RED_OFF);
    float* hvec = sm + HV_OFF;

    const int tid = threadIdx.x;
    const int j   = tid & 127;
    const int p   = tid >> 7;
    const int d   = blockIdx.x >> 6;
    const int b   = blockIdx.x & 63;
    const int kb  = p << 6;

    const float* W = whh + (size_t)d * 512 * 128;

    for (int idx = tid; idx < 128 * 128; idx += 256) {
        int rr = idx >> 7, k = idx & 127;
        float v = W[(size_t)(384 + rr) * 128 + k];
        Wo_s[((k >> 6) * 128 + rr) * WO_STRIDE + (k & 63)] = v;
    }

    ull Wi[32], Wf[32], Wg[32];
    {
        const float2* ri = reinterpret_cast<const float2*>(W + (size_t)(0   + j) * 128 + kb);
        const float2* rf = reinterpret_cast<const float2*>(W + (size_t)(128 + j) * 128 + kb);
        const float2* rg = reinterpret_cast<const float2*>(W + (size_t)(256 + j) * 128 + kb);
#pragma unroll
        for (int q = 0; q < 32; q++) {
            float2 a = ri[q]; Wi[q] = pk2(a.x, a.y);
            float2 f = rf[q]; Wf[q] = pk2(f.x, f.y);
            float2 gg = rg[q]; Wg[q] = pk2(gg.x, gg.y);
        }
    }

    float c = cx0[(size_t)(d * 64 + b) * 128 + j];
    if (tid < 128) hvec[tid] = hx0[(size_t)(d * 64 + b) * 128 + tid];
    __syncthreads();

    const int t0 = d ? (TT - 1) : 0;
    const int dt = d ? -1 : 1;
    const bool bwd_last = (final_layer && d);
    const int nsteps = bwd_last ? 1 : TT;
    const float* xgb = xg + ((size_t)d * MMM + (size_t)b * TT) * 512;

    float xi = 0.f, xf = 0.f, xgv = 0.f, xo = 0.f;
    if (p == 0) {
        const float* row = bwd_last ? (xgB + (size_t)b * 512)
                                    : (xgb + (size_t)t0 * 512);
        xi  = row[j];
        xf  = row[128 + j];
        xgv = row[256 + j];
        xo  = row[384 + j];
    }

    const float* worow = Wo_s + (size_t)tid * WO_STRIDE;
    const float* hbase = hvec + kb;

    for (int s = 0; s < nsteps; s++) {
        const int t = t0 + s * dt;

        ull aI = 0ull, aF = 0ull, aG = 0ull, aO = 0ull;
#pragma unroll
        for (int q4 = 0; q4 < 16; q4++) {
            ulonglong2 hq = *reinterpret_cast<const ulonglong2*>(hbase + 4 * q4);
            ulonglong2 wq = *reinterpret_cast<const ulonglong2*>(worow + 4 * q4);
            aI = fma2(hq.x, Wi[2 * q4], aI);
            aF = fma2(hq.x, Wf[2 * q4], aF);
            aG = fma2(hq.x, Wg[2 * q4], aG);
            aO = fma2(hq.x, wq.x,       aO);
            aI = fma2(hq.y, Wi[2 * q4 + 1], aI);
            aF = fma2(hq.y, Wf[2 * q4 + 1], aF);
            aG = fma2(hq.y, Wg[2 * q4 + 1], aG);
            aO = fma2(hq.y, wq.y,           aO);
        }
        red[0 * 256 + tid] = aI;
        red[1 * 256 + tid] = aF;
        red[2 * 256 + tid] = aG;
        red[3 * 256 + tid] = aO;
        __syncthreads();

        float nxi = 0.f, nxf = 0.f, nxg = 0.f, nxo = 0.f;
        if (p == 0 && s + 1 < nsteps) {
            const size_t bse = (size_t)(t + dt) * 512;
            nxi = xgb[bse + j];
            nxf = xgb[bse + 128 + j];
            nxg = xgb[bse + 256 + j];
            nxo = xgb[bse + 384 + j];
        }

        if (p == 0) {
            float ai = hsum2(add2(red[0 * 256 + j], red[0 * 256 + 128 + j])) + xi;
            float af = hsum2(add2(red[1 * 256 + j], red[1 * 256 + 128 + j])) + xf;
            float ag = hsum2(add2(red[2 * 256 + j], red[2 * 256 + 128 + j])) + xgv;
            float ao = hsum2(add2(red[3 * 256 + j], red[3 * 256 + 128 + j])) + xo;

            float ig = sig_a(ai);
            float fg = sig_a(af);
            float og = sig_a(ao);
            c = fmaf(fg, c, ig * tanh_a(ag));
            float hn = og * tanh_a(c);

            hvec[j] = hn;
            if (!final_layer) {
                y[((size_t)b * TT + t) * 256 + d * 128 + j] = hn;
            } else if (s == nsteps - 1) {
                y[(size_t)b * 256 + d * 128 + j] = hn;
            }
        }
        __syncthreads();

        xi = nxi; xf = nxf; xgv = nxg; xo = nxo;
    }
}

// ---------------------------------------------------------------------------
// Kernel 4: linear head
// ---------------------------------------------------------------------------
__global__ void head_k(const float* __restrict__ ylast,
                       const float* __restrict__ w,
                       const float* __restrict__ bsc,
                       float* __restrict__ out) {
    int b = blockIdx.x;
    int l = threadIdx.x;
    float s = 0.f;
#pragma unroll
    for (int k = l; k < 256; k += 32) s += ylast[(size_t)b * 256 + k] * w[k];
#pragma unroll
    for (int o = 16; o; o >>= 1) s += __shfl_xor_sync(0xffffffffu, s, o);
    if (l == 0) out[b] = s + bsc[0];
}

// ---------------------------------------------------------------------------
extern "C" void kernel_launch(void* const* d_in, const int* in_sizes, int n_in,
                              void* d_out, int out_size) {
    const int*   X     = (const int*)d_in[0];
    const float* emb   = (const float*)d_in[1];
    const float* hx    = (const float*)d_in[2];
    const float* cx    = (const float*)d_in[3];
    const float* lin_w = (const float*)d_in[4];
    const float* lin_b = (const float*)d_in[5];
    const float* w_ih[3] = {(const float*)d_in[6],  (const float*)d_in[10], (const float*)d_in[14]};
    const float* w_hh[3] = {(const float*)d_in[7],  (const float*)d_in[11], (const float*)d_in[15]};
    const float* b_ih[3] = {(const float*)d_in[8],  (const float*)d_in[12], (const float*)d_in[16]};
    const float* b_hh[3] = {(const float*)d_in[9],  (const float*)d_in[13], (const float*)d_in[17]};
    float* out = (float*)d_out;

    float *x0, *xgp, *xgB, *ya, *yb, *ylast, *biasp;
    __nv_bfloat16 *xc, *wc;
    cudaGetSymbolAddress((void**)&x0,    g_x0);
    cudaGetSymbolAddress((void**)&xgp,   g_xg);
    cudaGetSymbolAddress((void**)&xgB,   g_xgB);
    cudaGetSymbolAddress((void**)&ya,    g_ya);
    cudaGetSymbolAddress((void**)&yb,    g_yb);
    cudaGetSymbolAddress((void**)&ylast, g_ylast);
    cudaGetSymbolAddress((void**)&xc,    g_xc);
    cudaGetSymbolAddress((void**)&wc,    g_wc);
    cudaGetSymbolAddress((void**)&biasp, g_bias);

    cudaFuncSetAttribute(lstm2,
                         cudaFuncAttributeMaxDynamicSharedMemorySize, LSTM2_SMEM);

    // --- embed + layer-0 conversions ---------------------------------------
    embed_k<<<(MMM * 32) / 256, 256>>>(X, emb, x0);
    conv_x<<<(MMM * 128) / 256, 256>>>(x0, xc, 7);                 // K=128 -> K3=384
    conv_w<<<(1024 * 128) / 256, 256>>>(w_ih[0], wc, 7);
    bias_k<<<1024 / 256, 256>>>(b_ih[0], b_hh[0], biasp);

    // --- layer 0 ------------------------------------------------------------
    gemm_mma<<<dim3(8, 256), 256>>>(xc, wc, biasp, xgp, 384, 12);
    lstm2<<<128, 256, LSTM2_SMEM>>>(xgp, nullptr, w_hh[0], hx + 0 * BB * 128, cx + 0 * BB * 128, ya, 0);

    // --- layer 1 ------------------------------------------------------------
    conv_x<<<(MMM * 256) / 256, 256>>>(ya, xc, 8);                 // K=256 -> K3=768
    conv_w<<<(1024 * 256) / 256, 256>>>(w_ih[1], wc, 8);
    bias_k<<<1024 / 256, 256>>>(b_ih[1], b_hh[1], biasp);
    gemm_mma<<<dim3(8, 256), 256>>>(xc, wc, biasp, xgp, 768, 24);
    lstm2<<<128, 256, LSTM2_SMEM>>>(xgp, nullptr, w_hh[1], hx + 2 * BB * 128, cx + 2 * BB * 128, yb, 0);

    // --- layer 2 (fwd full via MMA GEMM; bwd last-t via fp32 GEMV) ----------
    conv_x<<<(MMM * 256) / 256, 256>>>(yb, xc, 8);
    conv_w<<<(512 * 256) / 256, 256>>>(w_ih[2], wc, 8);            // d=0 rows only
    bias_k<<<512 / 256, 256>>>(b_ih[2], b_hh[2], biasp);
    gemm_mma<<<dim3(4, 256), 256>>>(xc, wc, biasp, xgp, 768, 24);
    gemv_last<<<BB, 256>>>(yb, w_ih[2], b_ih[2], b_hh[2], xgB);
    lstm2<<<128, 256, LSTM2_SMEM>>>(xgp, xgB, w_hh[2], hx + 4 * BB * 128, cx + 4 * BB * 128, ylast, 1);

    head_k<<<BB, 32>>>(ylast, lin_w, lin_b, out);
}